// round 12
// baseline (speedup 1.0000x reference)
#include <cuda_runtime.h>
#include <cuda_fp16.h>

#define Bsz 128
#define Nn  1024
#define Mm  1024
#define TROWS  128             // rows per tile; 8 warps x 16 rows
#define NTILES 8               // 1024 / 128
#define INV_EPS 20.0f          // 1/0.05
#define STAB 1e-8f
#define NUM_ITERS 10
#define PSTRIDE ((size_t)Bsz * Mm)

// Scratch (allocation-free rule: __device__ globals)
__device__ __half d_K[(size_t)Bsz * Nn * Mm];            // 256 MB fp16 kernel matrix
__device__ float  d_u[Bsz * Nn];
__device__ float  d_v[Bsz * Mm];
__device__ float  d_part[(size_t)NTILES * Bsz * Mm];     // 4 MB per-tile column partials

// ---------------------------------------------------------------------------
// Pass 1: K = exp(-C/eps) in fp16 (two launches so ncu -s 5 profiles k_fused)
// ---------------------------------------------------------------------------
__global__ __launch_bounds__(256) void k_exp(const float* __restrict__ C, size_t off4, size_t cnt4) {
    size_t stride = (size_t)gridDim.x * blockDim.x;
    for (size_t i = (size_t)blockIdx.x * blockDim.x + threadIdx.x; i < cnt4; i += stride) {
        size_t idx = off4 + i;
        float4 c = reinterpret_cast<const float4*>(C)[idx];
        __half2 lo = __floats2half2_rn(__expf(-c.x * INV_EPS), __expf(-c.y * INV_EPS));
        __half2 hi = __floats2half2_rn(__expf(-c.z * INV_EPS), __expf(-c.w * INV_EPS));
        union { __half2 h[2]; uint2 u; } p;
        p.h[0] = lo; p.h[1] = hi;
        reinterpret_cast<uint2*>(d_K)[idx] = p.u;
    }
}

// init partials so first fused iteration sees v = 1/(8*128) = 1/1024
__global__ __launch_bounds__(256) void k_initpart() {
    size_t i = (size_t)blockIdx.x * 256 + threadIdx.x;
    reinterpret_cast<float4*>(d_part)[i] = make_float4(128.f, 128.f, 128.f, 128.f);
}

// ---------------------------------------------------------------------------
// Fused iteration (folds in the v-finalize of the PREVIOUS iteration):
// prologue: sv[c] = 1/(sum_t part[t][b][c] + eps)
// main (R6 single-convert form + next-row prefetch pipeline):
//   warp r = rr*8+warp. Load raw kvN for next row FIRST, then convert current
//   kv -> rowf[32], tree-dot with vreg, butterfly, u=rcp, colacc += rowf*u.
// epilogue: 8-warp smem reduction -> d_part[tile].
// ---------------------------------------------------------------------------
__global__ __launch_bounds__(256, 2) void k_fused() {
    __shared__ float sv[Mm];                 // 4 KB
    __shared__ float spart[8 * Mm];          // 32 KB

    int t = blockIdx.x;                      // tile 0..7
    int b = blockIdx.y;                      // batch 0..127
    int warp = threadIdx.x >> 5;
    int lane = threadIdx.x & 31;

    // ---- prologue: finalize v from previous iteration's partials ----
    {
        int c4 = threadIdx.x;                // float4 index [0,256)
        const float4* P = reinterpret_cast<const float4*>(d_part + (size_t)b * Mm);
        float4 s = make_float4(0.f, 0.f, 0.f, 0.f);
#pragma unroll
        for (int tt = 0; tt < NTILES; tt++) {
            float4 p = P[(PSTRIDE / 4) * tt + c4];
            s.x += p.x; s.y += p.y; s.z += p.z; s.w += p.w;
        }
        float4 o;
        o.x = 1.0f / (s.x + STAB);
        o.y = 1.0f / (s.y + STAB);
        o.z = 1.0f / (s.z + STAB);
        o.w = 1.0f / (s.w + STAB);
        reinterpret_cast<float4*>(sv)[c4] = o;
    }
    __syncthreads();

    // lane's 32 fixed columns of v -> registers
    float vreg[32];
#pragma unroll
    for (int j = 0; j < 4; j++) {
        int base = j * 256 + lane * 8;
        float4 a0 = *reinterpret_cast<const float4*>(sv + base);
        float4 a1 = *reinterpret_cast<const float4*>(sv + base + 4);
        vreg[j*8+0] = a0.x; vreg[j*8+1] = a0.y; vreg[j*8+2] = a0.z; vreg[j*8+3] = a0.w;
        vreg[j*8+4] = a1.x; vreg[j*8+5] = a1.y; vreg[j*8+6] = a1.z; vreg[j*8+7] = a1.w;
    }

    float colacc[32];
#pragma unroll
    for (int i = 0; i < 32; i++) colacc[i] = 0.0f;

    const __half* Ktile = d_K + ((size_t)b * Nn + t * TROWS) * Mm;

    // prefetch row 0 for this warp
    uint4 kv[4];
    {
        const __half* Krow = Ktile + (size_t)warp * Mm;
#pragma unroll
        for (int j = 0; j < 4; j++)
            kv[j] = *reinterpret_cast<const uint4*>(Krow + j * 256 + lane * 8);
    }

#pragma unroll 4
    for (int rr = 0; rr < 16; rr++) {
        int r = rr * 8 + warp;

        // issue next row's loads before touching current row's data
        int rNext = (rr < 15) ? (r + 8) : warp;      // last iter: dummy reload of row 'warp'
        uint4 kvN[4];
        {
            const __half* KrowN = Ktile + (size_t)rNext * Mm;
#pragma unroll
            for (int j = 0; j < 4; j++)
                kvN[j] = *reinterpret_cast<const uint4*>(KrowN + j * 256 + lane * 8);
        }

        // convert current row once
        float rowf[32];
#pragma unroll
        for (int j = 0; j < 4; j++) {
            union { uint4 u; __half2 h[4]; } p; p.u = kv[j];
#pragma unroll
            for (int q = 0; q < 4; q++) {
                float2 f = __half22float2(p.h[q]);
                rowf[j*8 + 2*q]     = f.x;
                rowf[j*8 + 2*q + 1] = f.y;
            }
        }

        // tree dot (4 independent chains)
        float p0 = 0.f, p1 = 0.f, p2 = 0.f, p3 = 0.f;
#pragma unroll
        for (int i = 0; i < 8; i++) {
            p0 += rowf[i]      * vreg[i];
            p1 += rowf[8 + i]  * vreg[8 + i];
            p2 += rowf[16 + i] * vreg[16 + i];
            p3 += rowf[24 + i] * vreg[24 + i];
        }
        float acc = (p0 + p1) + (p2 + p3);
#pragma unroll
        for (int o = 16; o > 0; o >>= 1) acc += __shfl_xor_sync(0xFFFFFFFFu, acc, o);

        float u = 1.0f / (acc + STAB);
        if (lane == 0) d_u[b * Nn + t * TROWS + r] = u;

#pragma unroll
        for (int i = 0; i < 32; i++) colacc[i] += rowf[i] * u;

        // rotate prefetch
#pragma unroll
        for (int j = 0; j < 4; j++) kv[j] = kvN[j];
    }

    // per-warp partials -> smem
#pragma unroll
    for (int j = 0; j < 4; j++) {
        float* dst = spart + warp * Mm + j * 256 + lane * 8;
        *reinterpret_cast<float4*>(dst)     = make_float4(colacc[j*8+0], colacc[j*8+1], colacc[j*8+2], colacc[j*8+3]);
        *reinterpret_cast<float4*>(dst + 4) = make_float4(colacc[j*8+4], colacc[j*8+5], colacc[j*8+6], colacc[j*8+7]);
    }
    __syncthreads();

    // block reduce 8 warps -> d_part[tile]
    {
        int c = threadIdx.x * 4;
        float4 s = make_float4(0.f, 0.f, 0.f, 0.f);
#pragma unroll
        for (int w = 0; w < 8; w++) {
            float4 p = *reinterpret_cast<const float4*>(spart + w * Mm + c);
            s.x += p.x; s.y += p.y; s.z += p.z; s.w += p.w;
        }
        *reinterpret_cast<float4*>(d_part + (size_t)t * PSTRIDE + b * Mm + c) = s;
    }
}

// ---------------------------------------------------------------------------
// Final v materialization (once, before k_out)
// ---------------------------------------------------------------------------
__global__ __launch_bounds__(256) void k_fin() {
    int i4 = blockIdx.x * 256 + threadIdx.x;   // [0, B*M/4)
    float4 s = make_float4(0.f, 0.f, 0.f, 0.f);
#pragma unroll
    for (int t = 0; t < NTILES; t++) {
        float4 p = reinterpret_cast<const float4*>(d_part + (size_t)t * PSTRIDE)[i4];
        s.x += p.x; s.y += p.y; s.z += p.z; s.w += p.w;
    }
    float4 o;
    o.x = 1.0f / (s.x + STAB);
    o.y = 1.0f / (s.y + STAB);
    o.z = 1.0f / (s.z + STAB);
    o.w = 1.0f / (s.w + STAB);
    reinterpret_cast<float4*>(d_v)[i4] = o;
}

// ---------------------------------------------------------------------------
// out = u[:,None] * K * v[None,:]   — K read back in fp16
// ---------------------------------------------------------------------------
__global__ __launch_bounds__(256) void k_out(float* __restrict__ out) {
    size_t n4 = (size_t)Bsz * Nn * Mm / 4;
    size_t stride = (size_t)gridDim.x * blockDim.x;
    for (size_t i = (size_t)blockIdx.x * blockDim.x + threadIdx.x; i < n4; i += stride) {
        size_t e   = i * 4;
        int    m   = (int)(e & (Mm - 1));
        size_t row = e >> 10;          // b*N + n
        int    b   = (int)(row >> 10);
        float  un  = d_u[row];
        union { uint2 u; __half2 h[2]; } p;
        p.u = reinterpret_cast<const uint2*>(d_K)[i];
        float2 k0 = __half22float2(p.h[0]);
        float2 k1 = __half22float2(p.h[1]);
        float4 vv = *reinterpret_cast<const float4*>(d_v + b * Mm + m);
        float4 o;
        o.x = un * k0.x * vv.x;
        o.y = un * k0.y * vv.y;
        o.z = un * k1.x * vv.z;
        o.w = un * k1.y * vv.w;
        reinterpret_cast<float4*>(out)[i] = o;
    }
}

extern "C" void kernel_launch(void* const* d_in, const int* in_sizes, int n_in,
                              void* d_out, int out_size) {
    const float* C   = (const float*)d_in[0];
    float*       out = (float*)d_out;

    size_t n4   = (size_t)Bsz * Nn * Mm / 4;
    size_t half = n4 / 2;
    k_exp<<<8192, 256>>>(C, 0, half);                       // 1
    k_exp<<<8192, 256>>>(C, half, half);                    // 2
    k_initpart<<<(NTILES * Bsz * Mm) / (4 * 256), 256>>>(); // 3
    dim3 grid(NTILES, Bsz);
    for (int it = 0; it < NUM_ITERS; it++)
        k_fused<<<grid, 256>>>();                           // 4..13 (6th launch = profiled)
    k_fin<<<(Bsz * Mm) / (4 * 256), 256>>>();
    k_out<<<8192, 256>>>(out);
}

// round 14
// speedup vs baseline: 1.3751x; 1.3751x over previous
#include <cuda_runtime.h>
#include <cuda_fp16.h>
#include <cstdint>

#define Bsz 128
#define Nn  1024
#define Mm  1024
#define TROWS  128             // rows per tile; 8 warps x 16 rows
#define NTILES 8               // 1024 / 128
#define INV_EPS 20.0f          // 1/0.05
#define STAB 1e-8f
#define NUM_ITERS 10
#define PSTRIDE ((size_t)Bsz * Mm)

// Scratch (allocation-free rule: __device__ globals)
__device__ __half d_K[(size_t)Bsz * Nn * Mm];            // 256 MB fp16 kernel matrix
__device__ float  d_u[Bsz * Nn];
__device__ float  d_v[Bsz * Mm];
__device__ float  d_part[(size_t)NTILES * Bsz * Mm];     // 4 MB per-tile column partials

__device__ __forceinline__ void cp_async16(unsigned int saddr, const __half* gaddr) {
    asm volatile("cp.async.cg.shared.global [%0], [%1], 16;\n" :: "r"(saddr), "l"(gaddr));
}
#define CP_COMMIT() asm volatile("cp.async.commit_group;\n" ::: "memory")
#define CP_WAIT3()  asm volatile("cp.async.wait_group 3;\n" ::: "memory")

// ---------------------------------------------------------------------------
// Pass 1: K = exp(-C/eps) in fp16 (two launches so ncu -s 5 profiles k_fused)
// ---------------------------------------------------------------------------
__global__ __launch_bounds__(256) void k_exp(const float* __restrict__ C, size_t off4, size_t cnt4) {
    size_t stride = (size_t)gridDim.x * blockDim.x;
    for (size_t i = (size_t)blockIdx.x * blockDim.x + threadIdx.x; i < cnt4; i += stride) {
        size_t idx = off4 + i;
        float4 c = reinterpret_cast<const float4*>(C)[idx];
        __half2 lo = __floats2half2_rn(__expf(-c.x * INV_EPS), __expf(-c.y * INV_EPS));
        __half2 hi = __floats2half2_rn(__expf(-c.z * INV_EPS), __expf(-c.w * INV_EPS));
        union { __half2 h[2]; uint2 u; } p;
        p.h[0] = lo; p.h[1] = hi;
        reinterpret_cast<uint2*>(d_K)[idx] = p.u;
    }
}

// init partials so first fused iteration sees v = 1/(8*128) = 1/1024
__global__ __launch_bounds__(256) void k_initpart() {
    size_t i = (size_t)blockIdx.x * 256 + threadIdx.x;
    reinterpret_cast<float4*>(d_part)[i] = make_float4(128.f, 128.f, 128.f, 128.f);
}

// ---------------------------------------------------------------------------
// Fused iteration (folds in the v-finalize of the PREVIOUS iteration).
// prologue: sv[c] = 1/(sum_t part[t][b][c] + eps)
// main: R6 loop, but rows stream through a per-warp 4-slot cp.async smem stage
//       (depth-3 prefetch, zero register cost). Each lane copies and reads
//       only its own 64 B per row -> per-thread wait_group is sufficient.
// epilogue: 8-warp smem reduction -> d_part[tile].
// Dynamic smem: sv 4KB | spart 32KB | stage 8 warps x 4 bufs x 2KB = 64KB.
// ---------------------------------------------------------------------------
__global__ __launch_bounds__(256, 2) void k_fused() {
    extern __shared__ char smemraw[];
    float*  sv    = reinterpret_cast<float*>(smemraw);                 // 4 KB
    float*  spart = reinterpret_cast<float*>(smemraw + 4096);          // 32 KB
    __half* stage = reinterpret_cast<__half*>(smemraw + 4096 + 32768); // 64 KB

    int t = blockIdx.x;                      // tile 0..7
    int b = blockIdx.y;                      // batch 0..127
    int warp = threadIdx.x >> 5;
    int lane = threadIdx.x & 31;

    // ---- prologue: finalize v from previous iteration's partials ----
    {
        int c4 = threadIdx.x;                // float4 index [0,256)
        const float4* P = reinterpret_cast<const float4*>(d_part + (size_t)b * Mm);
        float4 s = make_float4(0.f, 0.f, 0.f, 0.f);
#pragma unroll
        for (int tt = 0; tt < NTILES; tt++) {
            float4 p = P[(PSTRIDE / 4) * tt + c4];
            s.x += p.x; s.y += p.y; s.z += p.z; s.w += p.w;
        }
        float4 o;
        o.x = 1.0f / (s.x + STAB);
        o.y = 1.0f / (s.y + STAB);
        o.z = 1.0f / (s.z + STAB);
        o.w = 1.0f / (s.w + STAB);
        reinterpret_cast<float4*>(sv)[c4] = o;
    }
    __syncthreads();

    // lane's 32 fixed columns of v -> registers
    float vreg[32];
#pragma unroll
    for (int j = 0; j < 4; j++) {
        int base = j * 256 + lane * 8;
        float4 a0 = *reinterpret_cast<const float4*>(sv + base);
        float4 a1 = *reinterpret_cast<const float4*>(sv + base + 4);
        vreg[j*8+0] = a0.x; vreg[j*8+1] = a0.y; vreg[j*8+2] = a0.z; vreg[j*8+3] = a0.w;
        vreg[j*8+4] = a1.x; vreg[j*8+5] = a1.y; vreg[j*8+6] = a1.z; vreg[j*8+7] = a1.w;
    }

    float colacc[32];
#pragma unroll
    for (int i = 0; i < 32; i++) colacc[i] = 0.0f;

    const __half* Ktile = d_K + ((size_t)b * Nn + t * TROWS) * Mm;
    __half* mystage = stage + warp * (4 * Mm);          // 4 bufs x 1024 halves

    // prefetch iterations 0..2
#pragma unroll
    for (int d = 0; d < 3; d++) {
        const __half* Krow = Ktile + (size_t)(d * 8 + warp) * Mm;
        unsigned int sbase = (unsigned int)__cvta_generic_to_shared(mystage + d * Mm);
#pragma unroll
        for (int j = 0; j < 4; j++)
            cp_async16(sbase + (j * 256 + lane * 8) * 2, Krow + j * 256 + lane * 8);
        CP_COMMIT();
    }

#pragma unroll 4
    for (int rr = 0; rr < 16; rr++) {
        int r = rr * 8 + warp;

        // keep the pipeline 3 deep (empty commit at the tail keeps counts aligned)
        if (rr + 3 < 16) {
            const __half* KrowN = Ktile + (size_t)((rr + 3) * 8 + warp) * Mm;
            unsigned int sbase = (unsigned int)__cvta_generic_to_shared(mystage + ((rr + 3) & 3) * Mm);
#pragma unroll
            for (int j = 0; j < 4; j++)
                cp_async16(sbase + (j * 256 + lane * 8) * 2, KrowN + j * 256 + lane * 8);
        }
        CP_COMMIT();
        CP_WAIT3();

        // read this lane's 64 B of row rr from the stage, convert once
        const __half* buf = mystage + (rr & 3) * Mm;
        float rowf[32];
#pragma unroll
        for (int j = 0; j < 4; j++) {
            uint4 kv = *reinterpret_cast<const uint4*>(buf + j * 256 + lane * 8);
            union { uint4 u; __half2 h[4]; } p; p.u = kv;
#pragma unroll
            for (int q = 0; q < 4; q++) {
                float2 f = __half22float2(p.h[q]);
                rowf[j*8 + 2*q]     = f.x;
                rowf[j*8 + 2*q + 1] = f.y;
            }
        }

        // tree dot (4 independent chains)
        float p0 = 0.f, p1 = 0.f, p2 = 0.f, p3 = 0.f;
#pragma unroll
        for (int i = 0; i < 8; i++) {
            p0 += rowf[i]      * vreg[i];
            p1 += rowf[8 + i]  * vreg[8 + i];
            p2 += rowf[16 + i] * vreg[16 + i];
            p3 += rowf[24 + i] * vreg[24 + i];
        }
        float acc = (p0 + p1) + (p2 + p3);
#pragma unroll
        for (int o = 16; o > 0; o >>= 1) acc += __shfl_xor_sync(0xFFFFFFFFu, acc, o);

        float u = 1.0f / (acc + STAB);
        if (lane == 0) d_u[b * Nn + t * TROWS + r] = u;

#pragma unroll
        for (int i = 0; i < 32; i++) colacc[i] += rowf[i] * u;
    }

    // per-warp partials -> smem
#pragma unroll
    for (int j = 0; j < 4; j++) {
        float* dst = spart + warp * Mm + j * 256 + lane * 8;
        *reinterpret_cast<float4*>(dst)     = make_float4(colacc[j*8+0], colacc[j*8+1], colacc[j*8+2], colacc[j*8+3]);
        *reinterpret_cast<float4*>(dst + 4) = make_float4(colacc[j*8+4], colacc[j*8+5], colacc[j*8+6], colacc[j*8+7]);
    }
    __syncthreads();

    // block reduce 8 warps -> d_part[tile]
    {
        int c = threadIdx.x * 4;
        float4 s = make_float4(0.f, 0.f, 0.f, 0.f);
#pragma unroll
        for (int w = 0; w < 8; w++) {
            float4 p = *reinterpret_cast<const float4*>(spart + w * Mm + c);
            s.x += p.x; s.y += p.y; s.z += p.z; s.w += p.w;
        }
        *reinterpret_cast<float4*>(d_part + (size_t)t * PSTRIDE + b * Mm + c) = s;
    }
}

// ---------------------------------------------------------------------------
// Final v materialization (once, before k_out)
// ---------------------------------------------------------------------------
__global__ __launch_bounds__(256) void k_fin() {
    int i4 = blockIdx.x * 256 + threadIdx.x;   // [0, B*M/4)
    float4 s = make_float4(0.f, 0.f, 0.f, 0.f);
#pragma unroll
    for (int t = 0; t < NTILES; t++) {
        float4 p = reinterpret_cast<const float4*>(d_part + (size_t)t * PSTRIDE)[i4];
        s.x += p.x; s.y += p.y; s.z += p.z; s.w += p.w;
    }
    float4 o;
    o.x = 1.0f / (s.x + STAB);
    o.y = 1.0f / (s.y + STAB);
    o.z = 1.0f / (s.z + STAB);
    o.w = 1.0f / (s.w + STAB);
    reinterpret_cast<float4*>(d_v)[i4] = o;
}

// ---------------------------------------------------------------------------
// out = u[:,None] * K * v[None,:]   — K read back in fp16
// ---------------------------------------------------------------------------
__global__ __launch_bounds__(256) void k_out(float* __restrict__ out) {
    size_t n4 = (size_t)Bsz * Nn * Mm / 4;
    size_t stride = (size_t)gridDim.x * blockDim.x;
    for (size_t i = (size_t)blockIdx.x * blockDim.x + threadIdx.x; i < n4; i += stride) {
        size_t e   = i * 4;
        int    m   = (int)(e & (Mm - 1));
        size_t row = e >> 10;          // b*N + n
        int    b   = (int)(row >> 10);
        float  un  = d_u[row];
        union { uint2 u; __half2 h[2]; } p;
        p.u = reinterpret_cast<const uint2*>(d_K)[i];
        float2 k0 = __half22float2(p.h[0]);
        float2 k1 = __half22float2(p.h[1]);
        float4 vv = *reinterpret_cast<const float4*>(d_v + b * Mm + m);
        float4 o;
        o.x = un * k0.x * vv.x;
        o.y = un * k0.y * vv.y;
        o.z = un * k1.x * vv.z;
        o.w = un * k1.y * vv.w;
        reinterpret_cast<float4*>(out)[i] = o;
    }
}

extern "C" void kernel_launch(void* const* d_in, const int* in_sizes, int n_in,
                              void* d_out, int out_size) {
    const float* C   = (const float*)d_in[0];
    float*       out = (float*)d_out;

    const int SMEM_BYTES = 4096 + 32768 + 8 * 4 * Mm * 2;   // 102400
    static bool attr_set = false;
    if (!attr_set) {
        cudaFuncSetAttribute(k_fused, cudaFuncAttributeMaxDynamicSharedMemorySize, SMEM_BYTES);
        attr_set = true;
    }

    size_t n4   = (size_t)Bsz * Nn * Mm / 4;
    size_t half = n4 / 2;
    k_exp<<<8192, 256>>>(C, 0, half);                       // 1
    k_exp<<<8192, 256>>>(C, half, half);                    // 2
    k_initpart<<<(NTILES * Bsz * Mm) / (4 * 256), 256>>>(); // 3
    dim3 grid(NTILES, Bsz);
    for (int it = 0; it < NUM_ITERS; it++)
        k_fused<<<grid, 256, SMEM_BYTES>>>();               // 4..13 (6th launch = profiled)
    k_fin<<<(Bsz * Mm) / (4 * 256), 256>>>();
    k_out<<<8192, 256>>>(out);
}

// round 15
// speedup vs baseline: 1.5010x; 1.0915x over previous
#include <cuda_runtime.h>
#include <cuda_fp16.h>
#include <cstdint>

#define Bsz 128
#define Nn  1024
#define Mm  1024
#define TROWS  128             // rows per tile; 8 warps x 16 rows
#define NTILES 8               // 1024 / 128
#define STAB 1e-8f
#define NUM_ITERS 10
#define PSTRIDE ((size_t)Bsz * Mm)
#define NEG20_LOG2E (-28.853900817779268f)   // -20 * log2(e);  exp(-20c) = 2^(c*this)

// Scratch (allocation-free rule: __device__ globals)
__device__ __half d_K[(size_t)Bsz * Nn * Mm];            // 256 MB fp16 kernel matrix
__device__ float  d_u[Bsz * Nn];
__device__ float  d_v[Bsz * Mm];
__device__ float  d_part[(size_t)NTILES * Bsz * Mm];     // 4 MB per-tile column partials

__device__ __forceinline__ void cp_async16(unsigned int saddr, const void* gaddr) {
    asm volatile("cp.async.cg.shared.global [%0], [%1], 16;\n" :: "r"(saddr), "l"(gaddr));
}
#define CP_COMMIT() asm volatile("cp.async.commit_group;\n" ::: "memory")
#define CP_WAIT(n)  asm volatile("cp.async.wait_group %0;\n" :: "n"(n) : "memory")

union F2U { float2 f; unsigned long long u; };

__device__ __forceinline__ void ffma2(unsigned long long& d, unsigned long long a, unsigned long long b) {
    asm("fma.rn.f32x2 %0, %1, %2, %0;" : "+l"(d) : "l"(a), "l"(b));
}

// init partials so first fused iteration sees v = 1/(8*128) = 1/1024
__global__ __launch_bounds__(256) void k_initpart() {
    size_t i = (size_t)blockIdx.x * 256 + threadIdx.x;
    reinterpret_cast<float4*>(d_part)[i] = make_float4(128.f, 128.f, 128.f, 128.f);
}

// ---------------------------------------------------------------------------
// Iteration 1 fused with the exp pass: reads C (fp32) through a depth-2
// cp.async stage, computes K=exp2(C*NEG20_LOG2E) in fp32, writes fp16 K,
// and does the iteration-1 row-dot/colacc with uniform v=1/1024.
// smem: spart 32KB | stage 8 warps x 2 bufs x 4KB = 64KB  -> 96KB
// ---------------------------------------------------------------------------
__global__ __launch_bounds__(256, 2) void k_fused1(const float* __restrict__ C) {
    extern __shared__ char smemraw[];
    float* spart = reinterpret_cast<float*>(smemraw);                  // 32 KB
    float* stage = reinterpret_cast<float*>(smemraw + 32768);          // 64 KB

    int t = blockIdx.x, b = blockIdx.y;
    int warp = threadIdx.x >> 5, lane = threadIdx.x & 31;

    unsigned long long cacc[16];
    F2U zero; zero.f = make_float2(0.f, 0.f);
#pragma unroll
    for (int p = 0; p < 16; p++) cacc[p] = zero.u;
    F2U vp; vp.f = make_float2(1.0f / 1024.0f, 1.0f / 1024.0f);

    const float* Ctile = C + ((size_t)b * Nn + t * TROWS) * Mm;
    __half*      Ktile = d_K + ((size_t)b * Nn + t * TROWS) * Mm;
    float* mystage = stage + warp * (2 * Mm);     // 2 bufs x 1024 floats

    // prefetch row 0
    {
        const float* Crow = Ctile + (size_t)warp * Mm;
        unsigned int sbase = (unsigned int)__cvta_generic_to_shared(mystage);
#pragma unroll
        for (int j = 0; j < 8; j++)
            cp_async16(sbase + (j * 128 + lane * 4) * 4, Crow + j * 128 + lane * 4);
        CP_COMMIT();
    }

#pragma unroll 2
    for (int rr = 0; rr < 16; rr++) {
        int r = rr * 8 + warp;
        if (rr + 1 < 16) {
            const float* CrowN = Ctile + (size_t)((rr + 1) * 8 + warp) * Mm;
            unsigned int sbase = (unsigned int)__cvta_generic_to_shared(mystage + ((rr + 1) & 1) * Mm);
#pragma unroll
            for (int j = 0; j < 8; j++)
                cp_async16(sbase + (j * 128 + lane * 4) * 4, CrowN + j * 128 + lane * 4);
        }
        CP_COMMIT();
        CP_WAIT(1);

        const float* buf = mystage + (rr & 1) * Mm;
        __half* Krow = Ktile + (size_t)r * Mm;

        unsigned long long rowp[16];
#pragma unroll
        for (int j = 0; j < 4; j++) {
            float4 a = *reinterpret_cast<const float4*>(buf + j * 256 + lane * 8);
            float4 c = *reinterpret_cast<const float4*>(buf + j * 256 + lane * 8 + 4);
            F2U p0, p1, p2, p3;
            p0.f = make_float2(exp2f(a.x * NEG20_LOG2E), exp2f(a.y * NEG20_LOG2E));
            p1.f = make_float2(exp2f(a.z * NEG20_LOG2E), exp2f(a.w * NEG20_LOG2E));
            p2.f = make_float2(exp2f(c.x * NEG20_LOG2E), exp2f(c.y * NEG20_LOG2E));
            p3.f = make_float2(exp2f(c.z * NEG20_LOG2E), exp2f(c.w * NEG20_LOG2E));
            rowp[j*4+0] = p0.u; rowp[j*4+1] = p1.u; rowp[j*4+2] = p2.u; rowp[j*4+3] = p3.u;
            // write fp16 K (matching k_fused's read layout)
            union { uint4 u; __half2 h[4]; } w;
            w.h[0] = __floats2half2_rn(p0.f.x, p0.f.y);
            w.h[1] = __floats2half2_rn(p1.f.x, p1.f.y);
            w.h[2] = __floats2half2_rn(p2.f.x, p2.f.y);
            w.h[3] = __floats2half2_rn(p3.f.x, p3.f.y);
            *reinterpret_cast<uint4*>(Krow + j * 256 + lane * 8) = w.u;
        }

        // dot with uniform v (packed)
        unsigned long long ap[4] = {zero.u, zero.u, zero.u, zero.u};
#pragma unroll
        for (int p = 0; p < 16; p++) ffma2(ap[p & 3], rowp[p], vp.u);
        float acc;
        {
            F2U a0, a1, a2, a3; a0.u = ap[0]; a1.u = ap[1]; a2.u = ap[2]; a3.u = ap[3];
            acc = ((a0.f.x + a0.f.y) + (a1.f.x + a1.f.y)) + ((a2.f.x + a2.f.y) + (a3.f.x + a3.f.y));
        }
#pragma unroll
        for (int o = 16; o > 0; o >>= 1) acc += __shfl_xor_sync(0xFFFFFFFFu, acc, o);

        float u = 1.0f / (acc + STAB);
        if (lane == 0) d_u[b * Nn + t * TROWS + r] = u;

        F2U up; up.f = make_float2(u, u);
#pragma unroll
        for (int p = 0; p < 16; p++) ffma2(cacc[p], rowp[p], up.u);
    }

    // per-warp partials -> smem
#pragma unroll
    for (int j = 0; j < 4; j++) {
        float* dst = spart + warp * Mm + j * 256 + lane * 8;
        F2U q0, q1, q2, q3;
        q0.u = cacc[j*4+0]; q1.u = cacc[j*4+1]; q2.u = cacc[j*4+2]; q3.u = cacc[j*4+3];
        *reinterpret_cast<float4*>(dst)     = make_float4(q0.f.x, q0.f.y, q1.f.x, q1.f.y);
        *reinterpret_cast<float4*>(dst + 4) = make_float4(q2.f.x, q2.f.y, q3.f.x, q3.f.y);
    }
    __syncthreads();
    {
        int c = threadIdx.x * 4;
        float4 s = make_float4(0.f, 0.f, 0.f, 0.f);
#pragma unroll
        for (int w = 0; w < 8; w++) {
            float4 p = *reinterpret_cast<const float4*>(spart + w * Mm + c);
            s.x += p.x; s.y += p.y; s.z += p.z; s.w += p.w;
        }
        *reinterpret_cast<float4*>(d_part + (size_t)t * PSTRIDE + b * Mm + c) = s;
    }
}

// ---------------------------------------------------------------------------
// Fused iteration (iters 2..10): R14 structure + packed f32x2 FMA.
// ---------------------------------------------------------------------------
__global__ __launch_bounds__(256, 2) void k_fused() {
    extern __shared__ char smemraw[];
    float*  sv    = reinterpret_cast<float*>(smemraw);                 // 4 KB
    float*  spart = reinterpret_cast<float*>(smemraw + 4096);          // 32 KB
    __half* stage = reinterpret_cast<__half*>(smemraw + 4096 + 32768); // 64 KB

    int t = blockIdx.x, b = blockIdx.y;
    int warp = threadIdx.x >> 5, lane = threadIdx.x & 31;

    // ---- prologue: finalize v from previous iteration's partials ----
    {
        int c4 = threadIdx.x;
        const float4* P = reinterpret_cast<const float4*>(d_part + (size_t)b * Mm);
        float4 s = make_float4(0.f, 0.f, 0.f, 0.f);
#pragma unroll
        for (int tt = 0; tt < NTILES; tt++) {
            float4 p = P[(PSTRIDE / 4) * tt + c4];
            s.x += p.x; s.y += p.y; s.z += p.z; s.w += p.w;
        }
        float4 o;
        o.x = 1.0f / (s.x + STAB);
        o.y = 1.0f / (s.y + STAB);
        o.z = 1.0f / (s.z + STAB);
        o.w = 1.0f / (s.w + STAB);
        reinterpret_cast<float4*>(sv)[c4] = o;
    }
    __syncthreads();

    // lane's 32 fixed columns of v -> packed register pairs
    unsigned long long vp[16];
#pragma unroll
    for (int j = 0; j < 4; j++) {
        int base = j * 256 + lane * 8;
        float4 a0 = *reinterpret_cast<const float4*>(sv + base);
        float4 a1 = *reinterpret_cast<const float4*>(sv + base + 4);
        F2U q0, q1, q2, q3;
        q0.f = make_float2(a0.x, a0.y); q1.f = make_float2(a0.z, a0.w);
        q2.f = make_float2(a1.x, a1.y); q3.f = make_float2(a1.z, a1.w);
        vp[j*4+0] = q0.u; vp[j*4+1] = q1.u; vp[j*4+2] = q2.u; vp[j*4+3] = q3.u;
    }

    unsigned long long cacc[16];
    F2U zero; zero.f = make_float2(0.f, 0.f);
#pragma unroll
    for (int p = 0; p < 16; p++) cacc[p] = zero.u;

    const __half* Ktile = d_K + ((size_t)b * Nn + t * TROWS) * Mm;
    __half* mystage = stage + warp * (4 * Mm);

    // prefetch rows 0..2
#pragma unroll
    for (int d = 0; d < 3; d++) {
        const __half* Krow = Ktile + (size_t)(d * 8 + warp) * Mm;
        unsigned int sbase = (unsigned int)__cvta_generic_to_shared(mystage + d * Mm);
#pragma unroll
        for (int j = 0; j < 4; j++)
            cp_async16(sbase + (j * 256 + lane * 8) * 2, Krow + j * 256 + lane * 8);
        CP_COMMIT();
    }

#pragma unroll 4
    for (int rr = 0; rr < 16; rr++) {
        int r = rr * 8 + warp;
        if (rr + 3 < 16) {
            const __half* KrowN = Ktile + (size_t)((rr + 3) * 8 + warp) * Mm;
            unsigned int sbase = (unsigned int)__cvta_generic_to_shared(mystage + ((rr + 3) & 3) * Mm);
#pragma unroll
            for (int j = 0; j < 4; j++)
                cp_async16(sbase + (j * 256 + lane * 8) * 2, KrowN + j * 256 + lane * 8);
        }
        CP_COMMIT();
        CP_WAIT(3);

        const __half* buf = mystage + (rr & 3) * Mm;
        unsigned long long rowp[16];
#pragma unroll
        for (int j = 0; j < 4; j++) {
            uint4 kv = *reinterpret_cast<const uint4*>(buf + j * 256 + lane * 8);
            union { uint4 u; __half2 h[4]; } p; p.u = kv;
#pragma unroll
            for (int q = 0; q < 4; q++) {
                F2U f; f.f = __half22float2(p.h[q]);
                rowp[j*4+q] = f.u;
            }
        }

        // packed tree dot (4 independent f32x2 chains)
        unsigned long long ap[4] = {zero.u, zero.u, zero.u, zero.u};
#pragma unroll
        for (int p = 0; p < 16; p++) ffma2(ap[p & 3], rowp[p], vp[p]);
        float acc;
        {
            F2U a0, a1, a2, a3; a0.u = ap[0]; a1.u = ap[1]; a2.u = ap[2]; a3.u = ap[3];
            acc = ((a0.f.x + a0.f.y) + (a1.f.x + a1.f.y)) + ((a2.f.x + a2.f.y) + (a3.f.x + a3.f.y));
        }
#pragma unroll
        for (int o = 16; o > 0; o >>= 1) acc += __shfl_xor_sync(0xFFFFFFFFu, acc, o);

        float u = 1.0f / (acc + STAB);
        if (lane == 0) d_u[b * Nn + t * TROWS + r] = u;

        F2U up; up.f = make_float2(u, u);
#pragma unroll
        for (int p = 0; p < 16; p++) ffma2(cacc[p], rowp[p], up.u);
    }

    // per-warp partials -> smem
#pragma unroll
    for (int j = 0; j < 4; j++) {
        float* dst = spart + warp * Mm + j * 256 + lane * 8;
        F2U q0, q1, q2, q3;
        q0.u = cacc[j*4+0]; q1.u = cacc[j*4+1]; q2.u = cacc[j*4+2]; q3.u = cacc[j*4+3];
        *reinterpret_cast<float4*>(dst)     = make_float4(q0.f.x, q0.f.y, q1.f.x, q1.f.y);
        *reinterpret_cast<float4*>(dst + 4) = make_float4(q2.f.x, q2.f.y, q3.f.x, q3.f.y);
    }
    __syncthreads();
    {
        int c = threadIdx.x * 4;
        float4 s = make_float4(0.f, 0.f, 0.f, 0.f);
#pragma unroll
        for (int w = 0; w < 8; w++) {
            float4 p = *reinterpret_cast<const float4*>(spart + w * Mm + c);
            s.x += p.x; s.y += p.y; s.z += p.z; s.w += p.w;
        }
        *reinterpret_cast<float4*>(d_part + (size_t)t * PSTRIDE + b * Mm + c) = s;
    }
}

// ---------------------------------------------------------------------------
// Final v materialization (once, before k_out)
// ---------------------------------------------------------------------------
__global__ __launch_bounds__(256) void k_fin() {
    int i4 = blockIdx.x * 256 + threadIdx.x;
    float4 s = make_float4(0.f, 0.f, 0.f, 0.f);
#pragma unroll
    for (int t = 0; t < NTILES; t++) {
        float4 p = reinterpret_cast<const float4*>(d_part + (size_t)t * PSTRIDE)[i4];
        s.x += p.x; s.y += p.y; s.z += p.z; s.w += p.w;
    }
    float4 o;
    o.x = 1.0f / (s.x + STAB);
    o.y = 1.0f / (s.y + STAB);
    o.z = 1.0f / (s.z + STAB);
    o.w = 1.0f / (s.w + STAB);
    reinterpret_cast<float4*>(d_v)[i4] = o;
}

// ---------------------------------------------------------------------------
// out = u[:,None] * K * v[None,:]   — K read back in fp16
// ---------------------------------------------------------------------------
__global__ __launch_bounds__(256) void k_out(float* __restrict__ out) {
    size_t n4 = (size_t)Bsz * Nn * Mm / 4;
    size_t stride = (size_t)gridDim.x * blockDim.x;
    for (size_t i = (size_t)blockIdx.x * blockDim.x + threadIdx.x; i < n4; i += stride) {
        size_t e   = i * 4;
        int    m   = (int)(e & (Mm - 1));
        size_t row = e >> 10;
        int    b   = (int)(row >> 10);
        float  un  = d_u[row];
        union { uint2 u; __half2 h[2]; } p;
        p.u = reinterpret_cast<const uint2*>(d_K)[i];
        float2 k0 = __half22float2(p.h[0]);
        float2 k1 = __half22float2(p.h[1]);
        float4 vv = *reinterpret_cast<const float4*>(d_v + b * Mm + m);
        float4 o;
        o.x = un * k0.x * vv.x;
        o.y = un * k0.y * vv.y;
        o.z = un * k1.x * vv.z;
        o.w = un * k1.y * vv.w;
        reinterpret_cast<float4*>(out)[i] = o;
    }
}

extern "C" void kernel_launch(void* const* d_in, const int* in_sizes, int n_in,
                              void* d_out, int out_size) {
    const float* C   = (const float*)d_in[0];
    float*       out = (float*)d_out;

    const int SMEM_F  = 4096 + 32768 + 8 * 4 * Mm * 2;   // 102400 (k_fused)
    const int SMEM_F1 = 32768 + 8 * 2 * Mm * 4;          // 98304  (k_fused1)
    static bool attr_set = false;
    if (!attr_set) {
        cudaFuncSetAttribute(k_fused,  cudaFuncAttributeMaxDynamicSharedMemorySize, SMEM_F);
        cudaFuncSetAttribute(k_fused1, cudaFuncAttributeMaxDynamicSharedMemorySize, SMEM_F1);
        attr_set = true;
    }

    dim3 grid(NTILES, Bsz);
    k_initpart<<<(NTILES * Bsz * Mm) / (4 * 256), 256>>>();  // 1
    k_fused1<<<grid, 256, SMEM_F1>>>(C);                     // 2  (exp + iter 1)
    for (int it = 1; it < NUM_ITERS; it++)
        k_fused<<<grid, 256, SMEM_F>>>();                    // 3..11 (6th launch = plain fused)
    k_fin<<<(Bsz * Mm) / (4 * 256), 256>>>();
    k_out<<<8192, 256>>>(out);
}